// round 2
// baseline (speedup 1.0000x reference)
#include <cuda_runtime.h>

#define H 128
#define MAX_E 500000
#define MAX_N 50000
#define NPB 16   // nodes per block in output GEMM

// ---------------- scratch (device globals; no runtime allocation) ----------
__device__ float  g_e1[MAX_E];
__device__ float  g_e2[MAX_E];
__device__ float  g_e3[MAX_E];
__device__ float  g_s1[MAX_N];
__device__ float  g_s2[MAX_N];
__device__ float  g_s3[MAX_N];
__device__ float4 g_n1[MAX_N * 32];   // neigh accumulator, edge layer  (N x 128 f32)
__device__ float4 g_n2[MAX_N * 32];   // neigh accumulator, node layer
__device__ float4 g_n3[MAX_N * 32];   // neigh accumulator, comp layer

// ---------------- zero scratch --------------------------------------------
__global__ void k_zero(int n) {
    int tid    = blockIdx.x * blockDim.x + threadIdx.x;
    int stride = gridDim.x * blockDim.x;
    for (int j = tid; j < n; j += stride) {
        g_s1[j] = 0.f; g_s2[j] = 0.f; g_s3[j] = 0.f;
    }
    int tot = n * 32;
    float4 z = make_float4(0.f, 0.f, 0.f, 0.f);
    for (int j = tid; j < tot; j += stride) {
        g_n1[j] = z; g_n2[j] = z; g_n3[j] = z;
    }
}

// ---------------- pass 1: per-edge logits -> exp -> segment sums ----------
// warp per edge; lane l holds float4 chunk l of the 128-dim vectors.
__global__ void k_edge_logits(const float4* __restrict__ ent,
                              const float4* __restrict__ rel,
                              const int*    __restrict__ src,
                              const int*    __restrict__ dst,
                              const int*    __restrict__ rid,
                              int E) {
    int warp = blockIdx.x * (blockDim.x >> 5) + (threadIdx.x >> 5);
    int lane = threadIdx.x & 31;
    if (warp >= E) return;
    int s = src[warp], d = dst[warp], r = rid[warp];
    float4 u  = ent[s * 32 + lane];
    float4 v  = ent[d * 32 + lane];
    float4 rv = rel[r * 32 + lane];
    float du = u.x * v.x + u.y * v.y + u.z * v.z + u.w * v.w;
    float dr = rv.x * v.x + rv.y * v.y + rv.z * v.z + rv.w * v.w;
#pragma unroll
    for (int o = 16; o; o >>= 1) {
        du += __shfl_xor_sync(0xffffffffu, du, o);
        dr += __shfl_xor_sync(0xffffffffu, dr, o);
    }
    if (lane == 0) {
        // softmax is shift-invariant; logits are O(0.1) so no max-subtract needed.
        float a = __expf(dr);        // edge layer
        float b = __expf(du);        // node layer
        float c = a * b;             // comp layer: exp(du+dr)
        g_e1[warp] = a; g_e2[warp] = b; g_e3[warp] = c;
        atomicAdd(&g_s1[d], a);
        atomicAdd(&g_s2[d], b);
        atomicAdd(&g_s3[d], c);
    }
}

// ---------------- pass 2: weighted scatter-aggregate ----------------------
__device__ __forceinline__ void red_add_v4(float4* addr, float4 v) {
    asm volatile("red.global.add.v4.f32 [%0], {%1,%2,%3,%4};"
                 :: "l"(addr), "f"(v.x), "f"(v.y), "f"(v.z), "f"(v.w)
                 : "memory");
}

__global__ void k_edge_agg(const float4* __restrict__ ent,
                           const float4* __restrict__ rel,
                           const int*    __restrict__ src,
                           const int*    __restrict__ dst,
                           const int*    __restrict__ rid,
                           int E) {
    int warp = blockIdx.x * (blockDim.x >> 5) + (threadIdx.x >> 5);
    int lane = threadIdx.x & 31;
    if (warp >= E) return;
    int s = src[warp], d = dst[warp], r = rid[warp];
    float a1 = g_e1[warp] / g_s1[d];
    float a2 = g_e2[warp] / g_s2[d];
    float a3 = g_e3[warp] / g_s3[d];
    float4 u  = ent[s * 32 + lane];
    float4 rv = rel[r * 32 + lane];
    float4 c1 = make_float4(a1 * rv.x, a1 * rv.y, a1 * rv.z, a1 * rv.w);
    float4 c2 = make_float4(a2 * u.x,  a2 * u.y,  a2 * u.z,  a2 * u.w);
    float4 c3 = make_float4(a3 * (u.x + rv.x), a3 * (u.y + rv.y),
                            a3 * (u.z + rv.z), a3 * (u.w + rv.w));
    int o = d * 32 + lane;
    red_add_v4(&g_n1[o], c1);
    red_add_v4(&g_n2[o], c2);
    red_add_v4(&g_n3[o], c3);
}

// ---------------- pass 3: out = ent + sum_l tanh(neigh_l @ W_l) -----------
__device__ __forceinline__ void do_layer(const float* __restrict__ Nmat,
                                         const float* __restrict__ W,
                                         int base, int j,
                                         float (*sA)[H],
                                         float* outAcc) {
    __syncthreads();
#pragma unroll
    for (int t = 0; t < NPB; t++) sA[t][j] = Nmat[(base + t) * H + j];
    __syncthreads();
    float acc[NPB];
#pragma unroll
    for (int t = 0; t < NPB; t++) acc[t] = 0.f;
#pragma unroll 4
    for (int k = 0; k < H; k++) {
        float w = W[k * H + j];        // coalesced, L1-resident (192KB total)
#pragma unroll
        for (int t = 0; t < NPB; t++) acc[t] += sA[t][k] * w;  // smem broadcast
    }
#pragma unroll
    for (int t = 0; t < NPB; t++) outAcc[t] += tanhf(acc[t]);
}

__global__ void k_out(const float* __restrict__ ent,
                      const float* __restrict__ We,
                      const float* __restrict__ Wn,
                      const float* __restrict__ Wc,
                      float* __restrict__ out, int n) {
    __shared__ float sA[NPB][H];
    int j    = threadIdx.x;          // output column 0..127
    int base = blockIdx.x * NPB;     // first node of this block
    if (base >= n) return;
    float outAcc[NPB];
#pragma unroll
    for (int t = 0; t < NPB; t++) outAcc[t] = ent[(base + t) * H + j];

    do_layer((const float*)g_n1, We, base, j, sA, outAcc);
    do_layer((const float*)g_n2, Wn, base, j, sA, outAcc);
    do_layer((const float*)g_n3, Wc, base, j, sA, outAcc);

#pragma unroll
    for (int t = 0; t < NPB; t++) out[(base + t) * H + j] = outAcc[t];
}

// ---------------- launch ---------------------------------------------------
extern "C" void kernel_launch(void* const* d_in, const int* in_sizes, int n_in,
                              void* d_out, int out_size) {
    const float* ent = (const float*)d_in[0];
    const float* rel = (const float*)d_in[1];
    const float* We  = (const float*)d_in[2];
    const float* Wn  = (const float*)d_in[3];
    const float* Wc  = (const float*)d_in[4];
    const int*   src = (const int*)d_in[5];
    const int*   dst = (const int*)d_in[6];
    const int*   rid = (const int*)d_in[7];
    float*       out = (float*)d_out;

    int n = in_sizes[0] / H;      // 50000
    int E = in_sizes[5];          // 500000
    if (n > MAX_N) n = MAX_N;
    if (E > MAX_E) E = MAX_E;

    k_zero<<<2048, 256>>>(n);

    int eblocks = (E + 7) / 8;    // 8 warps (edges) per 256-thread block
    k_edge_logits<<<eblocks, 256>>>((const float4*)ent, (const float4*)rel,
                                    src, dst, rid, E);
    k_edge_agg<<<eblocks, 256>>>((const float4*)ent, (const float4*)rel,
                                 src, dst, rid, E);

    k_out<<<(n + NPB - 1) / NPB, H>>>(ent, We, Wn, Wc, out, n);
}

// round 4
// speedup vs baseline: 1.2594x; 1.2594x over previous
#include <cuda_runtime.h>

#define H 128
#define MAX_E 500000
#define MAX_N 50000
#define NPB 16   // nodes per block in output GEMM

// ---------------- scratch (device globals; no runtime allocation) ----------
__device__ float  g_s1[MAX_N];
__device__ float  g_s2[MAX_N];
__device__ float  g_s3[MAX_N];
__device__ float4 g_n1[MAX_N * 32];   // UNNORMALIZED neigh accum, edge layer
__device__ float4 g_n2[MAX_N * 32];   // node layer
__device__ float4 g_n3[MAX_N * 32];   // comp layer

// ---------------- zero scratch --------------------------------------------
__global__ void k_zero(int n) {
    int tid    = blockIdx.x * blockDim.x + threadIdx.x;
    int stride = gridDim.x * blockDim.x;
    for (int j = tid; j < n; j += stride) {
        g_s1[j] = 0.f; g_s2[j] = 0.f; g_s3[j] = 0.f;
    }
    int tot = n * 32;
    float4 z = make_float4(0.f, 0.f, 0.f, 0.f);
    for (int j = tid; j < tot; j += stride) {
        g_n1[j] = z; g_n2[j] = z; g_n3[j] = z;
    }
}

// ---------------- fused edge pass: logits -> exp -> scatter ----------------
// warp per edge; lane l holds float4 chunk l of the 128-dim vectors.
// Softmax normalization is deferred to k_out (divide by s[d] there).
__device__ __forceinline__ void red_add_v4(float4* addr, float4 v) {
    asm volatile("red.global.add.v4.f32 [%0], {%1,%2,%3,%4};"
                 :: "l"(addr), "f"(v.x), "f"(v.y), "f"(v.z), "f"(v.w)
                 : "memory");
}

__global__ void k_edge(const float4* __restrict__ ent,
                       const float4* __restrict__ rel,
                       const int*    __restrict__ src,
                       const int*    __restrict__ dst,
                       const int*    __restrict__ rid,
                       int E) {
    int warp = blockIdx.x * (blockDim.x >> 5) + (threadIdx.x >> 5);
    int lane = threadIdx.x & 31;
    if (warp >= E) return;
    int s = src[warp], d = dst[warp], r = rid[warp];
    float4 u  = ent[s * 32 + lane];
    float4 v  = ent[d * 32 + lane];
    float4 rv = rel[r * 32 + lane];
    float du = u.x * v.x + u.y * v.y + u.z * v.z + u.w * v.w;
    float dr = rv.x * v.x + rv.y * v.y + rv.z * v.z + rv.w * v.w;
#pragma unroll
    for (int o = 16; o; o >>= 1) {
        du += __shfl_xor_sync(0xffffffffu, du, o);
        dr += __shfl_xor_sync(0xffffffffu, dr, o);
    }
    // butterfly leaves the full sums in every lane.
    // logits are O(0.1): softmax shift-invariance => no max-subtract needed.
    float a1 = __expf(dr);          // edge layer weight
    float a2 = __expf(du);          // node layer weight
    float a3 = a1 * a2;             // comp layer: exp(du+dr)
    if (lane == 0) {
        atomicAdd(&g_s1[d], a1);
        atomicAdd(&g_s2[d], a2);
        atomicAdd(&g_s3[d], a3);
    }
    float4 c1 = make_float4(a1 * rv.x, a1 * rv.y, a1 * rv.z, a1 * rv.w);
    float4 c2 = make_float4(a2 * u.x,  a2 * u.y,  a2 * u.z,  a2 * u.w);
    float4 c3 = make_float4(a3 * (u.x + rv.x), a3 * (u.y + rv.y),
                            a3 * (u.z + rv.z), a3 * (u.w + rv.w));
    int o = d * 32 + lane;
    red_add_v4(&g_n1[o], c1);
    red_add_v4(&g_n2[o], c2);
    red_add_v4(&g_n3[o], c3);
}

// ---------------- pass 3: out = ent + sum_l tanh((raw_l @ W_l)/s_l) -------
__device__ __forceinline__ void do_layer(const float4* __restrict__ Nmat,
                                         const float*  __restrict__ Ssum,
                                         const float*  __restrict__ W,
                                         int base, int j,
                                         float4 (*sA)[32], float* sInv,
                                         float* outAcc) {
    __syncthreads();
    if (j < NPB) {
        float s = Ssum[base + j];
        // nodes with no incoming edges: s==0 and acc==0; use 0 so 0*0=0
        // (matches reference neigh=0), avoiding 0*inf=NaN.
        sInv[j] = (s > 0.f) ? (1.0f / s) : 0.f;
    }
#pragma unroll
    for (int t = 0; t < NPB; t++) {
        ((float*)&sA[t][0])[j] = ((const float*)&Nmat[(base + t) * 32])[j];
    }
    __syncthreads();
    float acc[NPB];
#pragma unroll
    for (int t = 0; t < NPB; t++) acc[t] = 0.f;
#pragma unroll 4
    for (int k4 = 0; k4 < 32; k4++) {
        float w0 = __ldg(&W[(4 * k4 + 0) * H + j]);
        float w1 = __ldg(&W[(4 * k4 + 1) * H + j]);
        float w2 = __ldg(&W[(4 * k4 + 2) * H + j]);
        float w3 = __ldg(&W[(4 * k4 + 3) * H + j]);
#pragma unroll
        for (int t = 0; t < NPB; t++) {
            float4 a = sA[t][k4];              // LDS.128 broadcast
            acc[t] += a.x * w0 + a.y * w1 + a.z * w2 + a.w * w3;
        }
    }
#pragma unroll
    for (int t = 0; t < NPB; t++) outAcc[t] += tanhf(acc[t] * sInv[t]);
}

__global__ void __launch_bounds__(H) k_out(const float* __restrict__ ent,
                      const float* __restrict__ We,
                      const float* __restrict__ Wn,
                      const float* __restrict__ Wc,
                      float* __restrict__ out, int n) {
    __shared__ float4 sA[NPB][32];
    __shared__ float  sInv[NPB];
    int j    = threadIdx.x;          // output column 0..127
    int base = blockIdx.x * NPB;     // first node of this block
    if (base >= n) return;
    float outAcc[NPB];
#pragma unroll
    for (int t = 0; t < NPB; t++) outAcc[t] = ent[(base + t) * H + j];

    do_layer(g_n1, g_s1, We, base, j, sA, sInv, outAcc);
    do_layer(g_n2, g_s2, Wn, base, j, sA, sInv, outAcc);
    do_layer(g_n3, g_s3, Wc, base, j, sA, sInv, outAcc);

#pragma unroll
    for (int t = 0; t < NPB; t++) out[(base + t) * H + j] = outAcc[t];
}

// ---------------- launch ---------------------------------------------------
extern "C" void kernel_launch(void* const* d_in, const int* in_sizes, int n_in,
                              void* d_out, int out_size) {
    const float* ent = (const float*)d_in[0];
    const float* rel = (const float*)d_in[1];
    const float* We  = (const float*)d_in[2];
    const float* Wn  = (const float*)d_in[3];
    const float* Wc  = (const float*)d_in[4];
    const int*   src = (const int*)d_in[5];
    const int*   dst = (const int*)d_in[6];
    const int*   rid = (const int*)d_in[7];
    float*       out = (float*)d_out;

    int n = in_sizes[0] / H;      // 50000
    int E = in_sizes[5];          // 500000
    if (n > MAX_N) n = MAX_N;
    if (E > MAX_E) E = MAX_E;

    k_zero<<<2048, 256>>>(n);

    int eblocks = (E + 7) / 8;    // 8 warps (edges) per 256-thread block
    k_edge<<<eblocks, 256>>>((const float4*)ent, (const float4*)rel,
                             src, dst, rid, E);

    k_out<<<(n + NPB - 1) / NPB, H>>>(ent, We, Wn, Wc, out, n);
}

// round 5
// speedup vs baseline: 1.3403x; 1.0642x over previous
#include <cuda_runtime.h>

#define H 128
#define MAX_E 500000
#define MAX_N 50000
#define NPB 16   // nodes per block in output GEMM

// ---------------- scratch (device globals; no runtime allocation) ----------
__device__ int    g_deg[MAX_N];        // per-node in-degree
__device__ int    g_cur[MAX_N];        // scatter cursors
__device__ int    g_off[MAX_N + 1];    // CSR offsets
__device__ int    g_eord[MAX_E];       // edge ids grouped by dst
__device__ float4 g_n1[MAX_N * 32];    // NORMALIZED neigh, edge layer (N x 128)
__device__ float4 g_n2[MAX_N * 32];    // node layer
__device__ float4 g_n3[MAX_N * 32];    // comp layer

// ---------------- clear counters ------------------------------------------
__global__ void k_clear(int n) {
    int i = blockIdx.x * blockDim.x + threadIdx.x;
    if (i < n) { g_deg[i] = 0; g_cur[i] = 0; }
}

// ---------------- histogram of dst ----------------------------------------
__global__ void k_hist(const int* __restrict__ dst, int E) {
    int e = blockIdx.x * blockDim.x + threadIdx.x;
    if (e < E) atomicAdd(&g_deg[dst[e]], 1);
}

// ---------------- single-block prefix scan (warp-cooperative) --------------
__global__ void k_scan(int n) {
    __shared__ int swarp[32];
    __shared__ int carry;
    int tid  = threadIdx.x;
    int lane = tid & 31;
    int wid  = tid >> 5;
    if (tid == 0) { carry = 0; g_off[0] = 0; }
    for (int base = 0; base < n; base += 1024) {
        __syncthreads();
        int c = carry;
        int i = base + tid;
        int x = (i < n) ? g_deg[i] : 0;
        int v = x;
#pragma unroll
        for (int o = 1; o < 32; o <<= 1) {
            int y = __shfl_up_sync(0xffffffffu, v, o);
            if (lane >= o) v += y;
        }
        if (lane == 31) swarp[wid] = v;
        __syncthreads();
        if (wid == 0) {
            int w = swarp[lane];
#pragma unroll
            for (int o = 1; o < 32; o <<= 1) {
                int y = __shfl_up_sync(0xffffffffu, w, o);
                if (lane >= o) w += y;
            }
            swarp[lane] = w;
        }
        __syncthreads();
        int pref = (wid > 0) ? swarp[wid - 1] : 0;
        if (i < n) g_off[i + 1] = c + pref + v;
        __syncthreads();
        if (tid == 0) carry = c + swarp[31];
    }
}

// ---------------- scatter edge ids into CSR order --------------------------
__global__ void k_scatter(const int* __restrict__ dst, int E) {
    int e = blockIdx.x * blockDim.x + threadIdx.x;
    if (e < E) {
        int d = dst[e];
        int pos = g_off[d] + atomicAdd(&g_cur[d], 1);
        g_eord[pos] = e;
    }
}

// ---------------- per-node aggregation: warp per dst node ------------------
// lane l holds float4 chunk l of the 128-dim vectors. No atomics, no shared
// accumulators: softmax sums and weighted message sums live in registers.
__global__ void k_agg(const float4* __restrict__ ent,
                      const float4* __restrict__ rel,
                      const int*    __restrict__ src,
                      const int*    __restrict__ rid,
                      int n) {
    int d    = blockIdx.x * (blockDim.x >> 5) + (threadIdx.x >> 5);
    int lane = threadIdx.x & 31;
    if (d >= n) return;
    int beg = g_off[d], end = g_off[d + 1];
    float4 v = ent[d * 32 + lane];

    float4 A1 = make_float4(0.f, 0.f, 0.f, 0.f);
    float4 A2 = A1, A3 = A1;
    float  S1 = 0.f, S2 = 0.f, S3 = 0.f;

    for (int i = beg; i < end; i++) {
        int e = g_eord[i];
        int s = src[e], r = rid[e];
        float4 u  = ent[s * 32 + lane];
        float4 rv = rel[r * 32 + lane];
        float du = u.x * v.x + u.y * v.y + u.z * v.z + u.w * v.w;
        float dr = rv.x * v.x + rv.y * v.y + rv.z * v.z + rv.w * v.w;
#pragma unroll
        for (int o = 16; o; o >>= 1) {
            du += __shfl_xor_sync(0xffffffffu, du, o);
            dr += __shfl_xor_sync(0xffffffffu, dr, o);
        }
        // logits are O(0.1): softmax shift-invariance => no max-subtract.
        float a1 = __expf(dr);     // edge layer weight
        float a2 = __expf(du);     // node layer weight
        float a3 = a1 * a2;        // comp layer: exp(du+dr)
        S1 += a1; S2 += a2; S3 += a3;
        A1.x += a1 * rv.x; A1.y += a1 * rv.y; A1.z += a1 * rv.z; A1.w += a1 * rv.w;
        A2.x += a2 * u.x;  A2.y += a2 * u.y;  A2.z += a2 * u.z;  A2.w += a2 * u.w;
        A3.x += a3 * (u.x + rv.x); A3.y += a3 * (u.y + rv.y);
        A3.z += a3 * (u.z + rv.z); A3.w += a3 * (u.w + rv.w);
    }
    float i1 = (S1 > 0.f) ? 1.0f / S1 : 0.f;
    float i2 = (S2 > 0.f) ? 1.0f / S2 : 0.f;
    float i3 = (S3 > 0.f) ? 1.0f / S3 : 0.f;
    int o = d * 32 + lane;
    g_n1[o] = make_float4(A1.x * i1, A1.y * i1, A1.z * i1, A1.w * i1);
    g_n2[o] = make_float4(A2.x * i2, A2.y * i2, A2.z * i2, A2.w * i2);
    g_n3[o] = make_float4(A3.x * i3, A3.y * i3, A3.z * i3, A3.w * i3);
}

// ---------------- pass 3: out = ent + sum_l tanh(neigh_l @ W_l) ------------
__device__ __forceinline__ void do_layer(const float4* __restrict__ Nmat,
                                         const float*  __restrict__ W,
                                         int base, int j,
                                         float4 (*sA)[32],
                                         float* outAcc) {
    __syncthreads();
#pragma unroll
    for (int t = 0; t < NPB; t++) {
        ((float*)&sA[t][0])[j] = ((const float*)&Nmat[(base + t) * 32])[j];
    }
    __syncthreads();
    float acc[NPB];
#pragma unroll
    for (int t = 0; t < NPB; t++) acc[t] = 0.f;
#pragma unroll 4
    for (int k4 = 0; k4 < 32; k4++) {
        float w0 = __ldg(&W[(4 * k4 + 0) * H + j]);
        float w1 = __ldg(&W[(4 * k4 + 1) * H + j]);
        float w2 = __ldg(&W[(4 * k4 + 2) * H + j]);
        float w3 = __ldg(&W[(4 * k4 + 3) * H + j]);
#pragma unroll
        for (int t = 0; t < NPB; t++) {
            float4 a = sA[t][k4];              // LDS.128 broadcast
            acc[t] += a.x * w0 + a.y * w1 + a.z * w2 + a.w * w3;
        }
    }
#pragma unroll
    for (int t = 0; t < NPB; t++) outAcc[t] += tanhf(acc[t]);
}

__global__ void __launch_bounds__(H) k_out(const float* __restrict__ ent,
                      const float* __restrict__ We,
                      const float* __restrict__ Wn,
                      const float* __restrict__ Wc,
                      float* __restrict__ out, int n) {
    __shared__ float4 sA[NPB][32];
    int j    = threadIdx.x;          // output column 0..127
    int base = blockIdx.x * NPB;     // first node of this block
    if (base >= n) return;
    float outAcc[NPB];
#pragma unroll
    for (int t = 0; t < NPB; t++) outAcc[t] = ent[(base + t) * H + j];

    do_layer(g_n1, We, base, j, sA, outAcc);
    do_layer(g_n2, Wn, base, j, sA, outAcc);
    do_layer(g_n3, Wc, base, j, sA, outAcc);

#pragma unroll
    for (int t = 0; t < NPB; t++) out[(base + t) * H + j] = outAcc[t];
}

// ---------------- launch ---------------------------------------------------
extern "C" void kernel_launch(void* const* d_in, const int* in_sizes, int n_in,
                              void* d_out, int out_size) {
    const float* ent = (const float*)d_in[0];
    const float* rel = (const float*)d_in[1];
    const float* We  = (const float*)d_in[2];
    const float* Wn  = (const float*)d_in[3];
    const float* Wc  = (const float*)d_in[4];
    const int*   src = (const int*)d_in[5];
    const int*   dst = (const int*)d_in[6];
    const int*   rid = (const int*)d_in[7];
    float*       out = (float*)d_out;

    int n = in_sizes[0] / H;      // 50000
    int E = in_sizes[5];          // 500000
    if (n > MAX_N) n = MAX_N;
    if (E > MAX_E) E = MAX_E;

    k_clear<<<(n + 255) / 256, 256>>>(n);
    k_hist<<<(E + 255) / 256, 256>>>(dst, E);
    k_scan<<<1, 1024>>>(n);
    k_scatter<<<(E + 255) / 256, 256>>>(dst, E);

    // warp per node: 8 nodes per 256-thread block
    k_agg<<<(n + 7) / 8, 256>>>((const float4*)ent, (const float4*)rel,
                                src, rid, n);

    k_out<<<(n + NPB - 1) / NPB, H>>>(ent, We, Wn, Wc, out, n);
}